// round 1
// baseline (speedup 1.0000x reference)
#include <cuda_runtime.h>

// Problem shape (fixed by reference):
//   article_concat: [256, 2048, 300] f32  (d_in[0])
//   options_concat: [256,   64, 300] f32  (d_in[1])
//   out:            [256, 600]       f32  = concat(mean(article,axis=1), mean(options,axis=1))

#define BATCH   256
#define WA      2048
#define WO      64
#define DIM     300
#define SPLIT   16
#define CHUNK   (WA / SPLIT)   // 128 words per partial block
#define NTHREADS 320           // 300 active, rounded to warp multiple

// Deterministic two-stage reduction scratch (no atomics, no allocation).
// 256 * 16 * 300 * 4B = 4.9 MB
__device__ float g_scratch[BATCH * SPLIT * DIM];

// Stage 1: each block sums CHUNK=128 words of one batch's article tensor.
// grid = (BATCH, SPLIT). Thread t owns feature column t (coalesced rows).
__global__ void __launch_bounds__(NTHREADS)
article_partial_kernel(const float* __restrict__ art) {
    const int b = blockIdx.x;
    const int c = blockIdx.y;
    const int t = threadIdx.x;
    if (t >= DIM) return;

    const float* __restrict__ p =
        art + ((size_t)b * WA + (size_t)c * CHUNK) * DIM + t;

    float s = 0.0f;
#pragma unroll 8
    for (int w = 0; w < CHUNK; ++w) {
        s += p[(size_t)w * DIM];
    }
    g_scratch[(b * SPLIT + c) * DIM + t] = s;
}

// Stage 2: reduce the 16 partials -> article mean, and directly mean-pool the
// (small) options tensor. Writes both halves of out; no zero-init needed.
// grid = BATCH.
__global__ void __launch_bounds__(NTHREADS)
finalize_kernel(const float* __restrict__ opt, float* __restrict__ out) {
    const int b = blockIdx.x;
    const int t = threadIdx.x;
    if (t >= DIM) return;

    // Article: sum 16 partials
    float s = 0.0f;
#pragma unroll
    for (int c = 0; c < SPLIT; ++c) {
        s += g_scratch[(b * SPLIT + c) * DIM + t];
    }
    out[(size_t)b * (2 * DIM) + t] = s * (1.0f / (float)WA);

    // Options: direct mean over 64 words
    const float* __restrict__ p = opt + (size_t)b * WO * DIM + t;
    float so = 0.0f;
#pragma unroll 8
    for (int w = 0; w < WO; ++w) {
        so += p[w * DIM];
    }
    out[(size_t)b * (2 * DIM) + DIM + t] = so * (1.0f / (float)WO);
}

extern "C" void kernel_launch(void* const* d_in, const int* in_sizes, int n_in,
                              void* d_out, int out_size) {
    const float* article = (const float*)d_in[0];
    const float* options = (const float*)d_in[1];
    float* out = (float*)d_out;

    dim3 grid1(BATCH, SPLIT);
    article_partial_kernel<<<grid1, NTHREADS>>>(article);
    finalize_kernel<<<BATCH, NTHREADS>>>(options, out);
}

// round 2
// speedup vs baseline: 1.1128x; 1.1128x over previous
#include <cuda_runtime.h>

// Shapes (fixed by reference):
//   article: [256, 2048, 300] f32  (d_in[0])
//   options: [256,   64, 300] f32  (d_in[1])
//   out:     [256, 600]       f32  = concat(mean(article,1), mean(options,1))

#define BATCH 256
#define WA    2048
#define WO    64
#define DIM   300
#define NV4   (DIM / 4)     // 75 float4 per feature row (rows are 16B-aligned: 1200B)
#define SPLIT 16
#define CHUNK (WA / SPLIT)  // 128 words per article partial block

// Deterministic two-stage scratch: 256*16*75 float4 = 4.9 MB. No atomics.
__device__ float4 g_scratch[BATCH * SPLIT * NV4];

// Stage 1: grid (BATCH, SPLIT+1), block (75, 4).
//  c in [0,16): sum CHUNK article words -> scratch partial
//  c == 16:     full options mean -> out[b, 300:600] directly
__global__ void __launch_bounds__(300)
stage1_kernel(const float* __restrict__ art, const float* __restrict__ opt,
              float* __restrict__ out) {
    const int b  = blockIdx.x;
    const int c  = blockIdx.y;
    const int tx = threadIdx.x;   // 0..74 -> float4 feature column
    const int ty = threadIdx.y;   // 0..3  -> row interleave phase

    __shared__ float4 red[4][NV4];

    if (c < SPLIT) {
        const float4* __restrict__ p = reinterpret_cast<const float4*>(
            art + ((size_t)b * WA + (size_t)c * CHUNK) * DIM) + tx;

        float4 s = make_float4(0.f, 0.f, 0.f, 0.f);
#pragma unroll 8
        for (int w = ty; w < CHUNK; w += 4) {
            float4 v = p[(size_t)w * NV4];
            s.x += v.x; s.y += v.y; s.z += v.z; s.w += v.w;
        }
        red[ty][tx] = s;
        __syncthreads();
        if (ty == 0) {
            float4 a = red[0][tx], b4 = red[1][tx], c4 = red[2][tx], d4 = red[3][tx];
            s.x = a.x + b4.x + c4.x + d4.x;
            s.y = a.y + b4.y + c4.y + d4.y;
            s.z = a.z + b4.z + c4.z + d4.z;
            s.w = a.w + b4.w + c4.w + d4.w;
            g_scratch[((size_t)b * SPLIT + c) * NV4 + tx] = s;
        }
    } else {
        // Options: 64 words, full mean, direct store.
        const float4* __restrict__ p = reinterpret_cast<const float4*>(
            opt + (size_t)b * WO * DIM) + tx;

        float4 s = make_float4(0.f, 0.f, 0.f, 0.f);
#pragma unroll 8
        for (int w = ty; w < WO; w += 4) {
            float4 v = p[(size_t)w * NV4];
            s.x += v.x; s.y += v.y; s.z += v.z; s.w += v.w;
        }
        red[ty][tx] = s;
        __syncthreads();
        if (ty == 0) {
            float4 a = red[0][tx], b4 = red[1][tx], c4 = red[2][tx], d4 = red[3][tx];
            const float inv = 1.0f / (float)WO;
            s.x = (a.x + b4.x + c4.x + d4.x) * inv;
            s.y = (a.y + b4.y + c4.y + d4.y) * inv;
            s.z = (a.z + b4.z + c4.z + d4.z) * inv;
            s.w = (a.w + b4.w + c4.w + d4.w) * inv;
            reinterpret_cast<float4*>(out + (size_t)b * (2 * DIM) + DIM)[tx] = s;
        }
    }
}

// Stage 2: grid BATCH, block (75,4). Reduce 16 article partials -> out[b, 0:300].
__global__ void __launch_bounds__(300)
stage2_kernel(float* __restrict__ out) {
    const int b  = blockIdx.x;
    const int tx = threadIdx.x;
    const int ty = threadIdx.y;

    __shared__ float4 red[4][NV4];

    float4 s = make_float4(0.f, 0.f, 0.f, 0.f);
#pragma unroll
    for (int c = ty; c < SPLIT; c += 4) {
        float4 v = g_scratch[((size_t)b * SPLIT + c) * NV4 + tx];
        s.x += v.x; s.y += v.y; s.z += v.z; s.w += v.w;
    }
    red[ty][tx] = s;
    __syncthreads();
    if (ty == 0) {
        float4 a = red[0][tx], b4 = red[1][tx], c4 = red[2][tx], d4 = red[3][tx];
        const float inv = 1.0f / (float)WA;
        s.x = (a.x + b4.x + c4.x + d4.x) * inv;
        s.y = (a.y + b4.y + c4.y + d4.y) * inv;
        s.z = (a.z + b4.z + c4.z + d4.z) * inv;
        s.w = (a.w + b4.w + c4.w + d4.w) * inv;
        reinterpret_cast<float4*>(out + (size_t)b * (2 * DIM))[tx] = s;
    }
}

extern "C" void kernel_launch(void* const* d_in, const int* in_sizes, int n_in,
                              void* d_out, int out_size) {
    const float* article = (const float*)d_in[0];
    const float* options = (const float*)d_in[1];
    float* out = (float*)d_out;

    dim3 block(NV4, 4);          // 300 threads
    dim3 grid1(BATCH, SPLIT + 1);
    stage1_kernel<<<grid1, block>>>(article, options, out);
    stage2_kernel<<<BATCH, block>>>(out);
}